// round 9
// baseline (speedup 1.0000x reference)
#include <cuda_runtime.h>
#include <cuda_fp16.h>
#include <cstdint>

// Shapes fixed by dataset: q/k (4,16,4096,64) f32, cos/sin (4,4096,64) f32, vs (32,64) f32
#define DD 64
#define SSS 4096
#define NROWS_Q (4*16*4096)    // 262144
#define NROWS_T (2*NROWS_Q)    // 524288
#define NREFL 32
#define NCHUNK 4096            // (tensor, b, s-chunk-of-8) work units
#define GRID 456               // 3 blocks x 152 SMs, persistent

// mma-ready packed fp16 B fragments, uint2 = {b0, b1}
// GEMM1: B1[k=j][n=i] = Q[i][j]   (Y = X * Q^T)
// GEMM2: B2[k=i][n=j] = Q[i][j]   (O = Z * Q)
__device__ uint2 g_B1[1024];
__device__ uint2 g_B2[1024];

// ---------------- cp.async helpers ----------------
__device__ __forceinline__ void cp_async16(uint32_t dst, const void* src) {
    asm volatile("cp.async.cg.shared.global [%0], [%1], 16;" :: "r"(dst), "l"(src));
}
__device__ __forceinline__ void cp_async_commit() {
    asm volatile("cp.async.commit_group;" ::: "memory");
}
__device__ __forceinline__ void cp_async_wait0() {
    asm volatile("cp.async.wait_group 0;" ::: "memory");
}
__device__ __forceinline__ void cp_async_wait1() {
    asm volatile("cp.async.wait_group 1;" ::: "memory");
}

// ---------------- Kernel A: build Q, barrier-free column-owner scan ----------------
__global__ void build_q_kernel(const float* __restrict__ vs) {
    __shared__ __align__(16) float vsh[NREFL*DD];
    __shared__ float coefs[NREFL];
    __shared__ float Qs[DD*DD];
    const int tid  = threadIdx.x;       // 256
    const int lane = tid & 31;
    const int warp = tid >> 5;

    for (int i = tid; i < NREFL*DD/4; i += 256)
        ((float4*)vsh)[i] = ((const float4*)vs)[i];
    __syncthreads();
    if (tid < NREFL) {
        float s = 0.0f;
        const float4* v4 = (const float4*)&vsh[tid*DD];
        #pragma unroll
        for (int c = 0; c < 16; ++c) {
            float4 v = v4[c];
            s += v.x*v.x + v.y*v.y + v.z*v.z + v.w*v.w;
        }
        coefs[tid] = 2.0f / (s + 1e-8f);
    }
    __syncthreads();

    if (warp < 4) {
        const int col = (warp << 4) | (lane & 15);
        const int seg = lane >> 4;
        float qc[32];
        #pragma unroll
        for (int i = 0; i < 32; ++i) qc[i] = (seg*32 + i == col) ? 1.0f : 0.0f;

        for (int r = 0; r < NREFL; ++r) {
            const float4* v4 = (const float4*)&vsh[r*DD + seg*32];
            float4 vv[8];
            #pragma unroll
            for (int i = 0; i < 8; ++i) vv[i] = v4[i];
            float w0 = 0.f, w1 = 0.f, w2 = 0.f, w3 = 0.f;
            #pragma unroll
            for (int i = 0; i < 8; ++i) {
                w0 += vv[i].x * qc[4*i];
                w1 += vv[i].y * qc[4*i+1];
                w2 += vv[i].z * qc[4*i+2];
                w3 += vv[i].w * qc[4*i+3];
            }
            float w = (w0 + w1) + (w2 + w3);
            w += __shfl_xor_sync(0xffffffffu, w, 16);
            float cw = coefs[r] * w;
            #pragma unroll
            for (int i = 0; i < 8; ++i) {
                qc[4*i]   -= vv[i].x * cw;
                qc[4*i+1] -= vv[i].y * cw;
                qc[4*i+2] -= vv[i].z * cw;
                qc[4*i+3] -= vv[i].w * cw;
            }
        }
        #pragma unroll
        for (int i = 0; i < 32; ++i) Qs[(seg*32 + i)*DD + col] = qc[i];
    }
    __syncthreads();

    for (int slot = tid; slot < 1024; slot += 256) {
        int l = slot & 31, frag = slot >> 5;
        int kt = frag >> 3, nt = frag & 7;
        int g = l >> 2, t4 = l & 3;
        int n  = 8*nt + g;
        int k0 = 16*kt + 2*t4;
        {
            __half2 h0 = __floats2half2_rn(Qs[n*DD + k0],     Qs[n*DD + k0 + 1]);
            __half2 h1 = __floats2half2_rn(Qs[n*DD + k0 + 8], Qs[n*DD + k0 + 9]);
            g_B1[slot] = make_uint2(*(uint32_t*)&h0, *(uint32_t*)&h1);
        }
        {
            __half2 h0 = __floats2half2_rn(Qs[k0*DD + n],     Qs[(k0+1)*DD + n]);
            __half2 h1 = __floats2half2_rn(Qs[(k0+8)*DD + n], Qs[(k0+9)*DD + n]);
            g_B2[slot] = make_uint2(*(uint32_t*)&h0, *(uint32_t*)&h1);
        }
    }
}

// ---------------- helpers ----------------
__device__ __forceinline__ void split_f16x2(float a, float b, uint32_t& hi, uint32_t& lo) {
    __half2 h = __floats2half2_rn(a, b);
    float2 hf = __half22float2(h);
    __half2 l = __floats2half2_rn(a - hf.x, b - hf.y);
    hi = *(uint32_t*)&h;
    lo = *(uint32_t*)&l;
}

#define MMA_F16(c, a0, a1, a2, a3, b0, b1)                                         \
    asm volatile("mma.sync.aligned.m16n8k16.row.col.f32.f16.f16.f32 "              \
                 "{%0,%1,%2,%3}, {%4,%5,%6,%7}, {%8,%9}, {%0,%1,%2,%3};"           \
                 : "+f"(c[0]), "+f"(c[1]), "+f"(c[2]), "+f"(c[3])                   \
                 : "r"(a0), "r"(a1), "r"(a2), "r"(a3), "r"(b0), "r"(b1))

// ---------------- Kernel B: persistent, 2-stage cp.async pipeline ----------------
// Dynamic smem layout (floats): xs[2][128*64] | cs[2][8*64] | ss[2][8*64]
// All tiles XOR-swizzled: element (row, col) stored at col ^ (4*(row&7)).
#define XS_OFF(p)  ((p) * 8192)
#define CS_OFF(p)  (16384 + (p) * 512)
#define SS_OFF(p)  (17408 + (p) * 512)
#define SMEM_FLOATS 18432     // 73728 bytes

__global__ void __launch_bounds__(128, 3) rnrope_mma_kernel(
    const float* __restrict__ qin, const float* __restrict__ kin,
    const float* __restrict__ cosp, const float* __restrict__ sinp,
    float* __restrict__ out)
{
    extern __shared__ __align__(16) float smem[];
    const uint32_t smbase = (uint32_t)__cvta_generic_to_shared(smem);

    const int tid  = threadIdx.x;
    const int warp = tid >> 5;
    const int lane = tid & 31;
    const int g    = lane >> 2;
    const int t4   = lane & 3;

    // ---- prefetch issue lambda (x + cos/sin for chunk c into stage p) ----
    auto prefetch = [&](int p, int c) {
        const int tensor = c >> 11;
        const int b      = (c >> 9) & 3;
        const int s0     = (c & 511) << 3;
        const float* src = tensor ? kin : qin;
        #pragma unroll
        for (int it = 0; it < 16; ++it) {
            int lin = it * 128 + tid;
            int rl  = lin >> 4;
            int c4  = (lin & 15) << 2;
            int h   = rl >> 3, ds = rl & 7;
            size_t gofs = (((size_t)(b * 16 + h)) * SSS + s0 + ds) * DD + c4;
            uint32_t dst = smbase + (uint32_t)(XS_OFF(p) + rl * 64 + (c4 ^ (ds << 2))) * 4u;
            cp_async16(dst, src + gofs);
        }
        {
            int r  = tid >> 4;
            int c4 = (tid & 15) << 2;
            size_t gofs = ((size_t)(b * SSS + s0 + r)) * DD + c4;
            int sw = c4 ^ (r << 2);
            cp_async16(smbase + (uint32_t)(CS_OFF(p) + r * 64 + sw) * 4u, cosp + gofs);
            cp_async16(smbase + (uint32_t)(SS_OFF(p) + r * 64 + sw) * 4u, sinp + gofs);
        }
        cp_async_commit();
    };

    int c = blockIdx.x;
    int p = 0;
    prefetch(p, c);

    while (true) {
        const int cn = c + GRID;
        const bool has_next = (cn < NCHUNK);
        if (has_next) { prefetch(p ^ 1, cn); cp_async_wait1(); }
        else          { cp_async_wait0(); }
        __syncthreads();

        const int tensor = c >> 11;
        const int b      = (c >> 9) & 3;
        const int s0     = (c & 511) << 3;
        float* xsp = smem + XS_OFF(p);
        const float* csp = smem + CS_OFF(p);
        const float* ssp = smem + SS_OFF(p);

        // ---- A1 fragments for the warp's two tiles ----
        const int sgw = g << 2;   // row swizzle (rows tb+g and tb+g+8 share it)
        uint32_t Ahi[2][4][4], Alo[2][4][4];
        #pragma unroll
        for (int tt = 0; tt < 2; ++tt) {
            int tb = (warp * 2 + tt) * 16;
            const float* x0 = xsp + (tb + g) * 64;
            const float* x1 = x0 + 8 * 64;
            #pragma unroll
            for (int kt = 0; kt < 4; ++kt) {
                int c0 = kt * 16 + 2 * t4;
                int sa = c0 ^ sgw;
                int sb = (c0 + 8) ^ sgw;
                float2 p00 = *(const float2*)(x0 + sa);
                float2 p01 = *(const float2*)(x0 + sb);
                float2 p10 = *(const float2*)(x1 + sa);
                float2 p11 = *(const float2*)(x1 + sb);
                split_f16x2(p00.x, p00.y, Ahi[tt][kt][0], Alo[tt][kt][0]);
                split_f16x2(p10.x, p10.y, Ahi[tt][kt][1], Alo[tt][kt][1]);
                split_f16x2(p01.x, p01.y, Ahi[tt][kt][2], Alo[tt][kt][2]);
                split_f16x2(p11.x, p11.y, Ahi[tt][kt][3], Alo[tt][kt][3]);
            }
        }

        // ---- GEMM1: Y = X * Q^T (2-term fp16) ----
        float C0[8][4], C1[8][4];
        #pragma unroll
        for (int nt = 0; nt < 8; ++nt)
            #pragma unroll
            for (int e = 0; e < 4; ++e) { C0[nt][e] = 0.0f; C1[nt][e] = 0.0f; }

        #pragma unroll
        for (int kt = 0; kt < 4; ++kt) {
            uint2 bb[8];
            #pragma unroll
            for (int nt = 0; nt < 8; ++nt) bb[nt] = g_B1[(kt*8 + nt)*32 + lane];
            #pragma unroll
            for (int nt = 0; nt < 8; ++nt) {
                MMA_F16(C0[nt], Ahi[0][kt][0], Ahi[0][kt][1], Ahi[0][kt][2], Ahi[0][kt][3], bb[nt].x, bb[nt].y);
                MMA_F16(C1[nt], Ahi[1][kt][0], Ahi[1][kt][1], Ahi[1][kt][2], Ahi[1][kt][3], bb[nt].x, bb[nt].y);
            }
            #pragma unroll
            for (int nt = 0; nt < 8; ++nt) {
                MMA_F16(C0[nt], Alo[0][kt][0], Alo[0][kt][1], Alo[0][kt][2], Alo[0][kt][3], bb[nt].x, bb[nt].y);
                MMA_F16(C1[nt], Alo[1][kt][0], Alo[1][kt][1], Alo[1][kt][2], Alo[1][kt][3], bb[nt].x, bb[nt].y);
            }
        }

        // ---- rope ----
        {
            const float* cr = csp + g * 64;
            const float* sr = ssp + g * 64;
            #pragma unroll
            for (int nt = 0; nt < 4; ++nt) {
                int cc  = 8*nt + 2*t4;
                int scl = cc ^ sgw;           // (cc+32)^sgw == scl+32 since sgw < 32
                float2 cl = *(const float2*)(cr + scl);
                float2 ch = *(const float2*)(cr + scl + 32);
                float2 sl = *(const float2*)(sr + scl);
                float2 sh = *(const float2*)(sr + scl + 32);
                #pragma unroll
                for (int e = 0; e < 4; ++e) {
                    float cle = (e & 1) ? cl.y : cl.x;
                    float che = (e & 1) ? ch.y : ch.x;
                    float sle = (e & 1) ? sl.y : sl.x;
                    float she = (e & 1) ? sh.y : sh.x;
                    float ylo0 = C0[nt][e], yhi0 = C0[nt+4][e];
                    C0[nt][e]   = ylo0*cle - yhi0*sle;
                    C0[nt+4][e] = yhi0*che + ylo0*she;
                    float ylo1 = C1[nt][e], yhi1 = C1[nt+4][e];
                    C1[nt][e]   = ylo1*cle - yhi1*sle;
                    C1[nt+4][e] = yhi1*che + ylo1*she;
                }
            }
        }

        // ---- Z -> A2 fragments ----
        #pragma unroll
        for (int kt = 0; kt < 4; ++kt) {
            split_f16x2(C0[2*kt][0],   C0[2*kt][1],   Ahi[0][kt][0], Alo[0][kt][0]);
            split_f16x2(C0[2*kt][2],   C0[2*kt][3],   Ahi[0][kt][1], Alo[0][kt][1]);
            split_f16x2(C0[2*kt+1][0], C0[2*kt+1][1], Ahi[0][kt][2], Alo[0][kt][2]);
            split_f16x2(C0[2*kt+1][2], C0[2*kt+1][3], Ahi[0][kt][3], Alo[0][kt][3]);
            split_f16x2(C1[2*kt][0],   C1[2*kt][1],   Ahi[1][kt][0], Alo[1][kt][0]);
            split_f16x2(C1[2*kt][2],   C1[2*kt][3],   Ahi[1][kt][1], Alo[1][kt][1]);
            split_f16x2(C1[2*kt+1][0], C1[2*kt+1][1], Ahi[1][kt][2], Alo[1][kt][2]);
            split_f16x2(C1[2*kt+1][2], C1[2*kt+1][3], Ahi[1][kt][3], Alo[1][kt][3]);
        }

        // ---- GEMM2: O = Z * Q ----
        #pragma unroll
        for (int nt = 0; nt < 8; ++nt)
            #pragma unroll
            for (int e = 0; e < 4; ++e) { C0[nt][e] = 0.0f; C1[nt][e] = 0.0f; }

        #pragma unroll
        for (int kt = 0; kt < 4; ++kt) {
            uint2 bb[8];
            #pragma unroll
            for (int nt = 0; nt < 8; ++nt) bb[nt] = g_B2[(kt*8 + nt)*32 + lane];
            #pragma unroll
            for (int nt = 0; nt < 8; ++nt) {
                MMA_F16(C0[nt], Ahi[0][kt][0], Ahi[0][kt][1], Ahi[0][kt][2], Ahi[0][kt][3], bb[nt].x, bb[nt].y);
                MMA_F16(C1[nt], Ahi[1][kt][0], Ahi[1][kt][1], Ahi[1][kt][2], Ahi[1][kt][3], bb[nt].x, bb[nt].y);
            }
            #pragma unroll
            for (int nt = 0; nt < 8; ++nt) {
                MMA_F16(C0[nt], Alo[0][kt][0], Alo[0][kt][1], Alo[0][kt][2], Alo[0][kt][3], bb[nt].x, bb[nt].y);
                MMA_F16(C1[nt], Alo[1][kt][0], Alo[1][kt][1], Alo[1][kt][2], Alo[1][kt][3], bb[nt].x, bb[nt].y);
            }
        }

        // ---- store: fragments -> smem (reuse current xs), then coalesced flush ----
        __syncthreads();   // all warps done reading xs/cs/ss of this stage
        #pragma unroll
        for (int tt = 0; tt < 2; ++tt) {
            int tb = (warp * 2 + tt) * 16;
            float* o0 = xsp + (tb + g) * 64;
            float* o1 = o0 + 8 * 64;
            #pragma unroll
            for (int nt = 0; nt < 8; ++nt) {
                int cc = 8*nt + 2*t4;
                int sc = cc ^ sgw;
                float2 v0, v1;
                if (tt == 0) { v0.x = C0[nt][0]; v0.y = C0[nt][1]; v1.x = C0[nt][2]; v1.y = C0[nt][3]; }
                else         { v0.x = C1[nt][0]; v0.y = C1[nt][1]; v1.x = C1[nt][2]; v1.y = C1[nt][3]; }
                *(float2*)(o0 + sc) = v0;
                *(float2*)(o1 + sc) = v1;
            }
        }
        __syncthreads();

        const size_t obase = (size_t)tensor * NROWS_Q * DD;
        #pragma unroll
        for (int it = 0; it < 16; ++it) {
            int lin = it * 128 + tid;
            int rl  = lin >> 4;
            int c4  = (lin & 15) << 2;
            int h   = rl >> 3, ds = rl & 7;
            float4 v = *(const float4*)(xsp + rl * 64 + (c4 ^ (ds << 2)));
            size_t gofs = obase + (((size_t)(b * 16 + h)) * SSS + s0 + ds) * DD + c4;
            *(float4*)(out + gofs) = v;
        }
        __syncthreads();   // xs(p) free for the prefetch two iterations ahead

        if (!has_next) break;
        c = cn;
        p ^= 1;
    }
}

extern "C" void kernel_launch(void* const* d_in, const int* in_sizes, int n_in,
                              void* d_out, int out_size) {
    const float* q    = (const float*)d_in[0];
    const float* k    = (const float*)d_in[1];
    const float* cosp = (const float*)d_in[2];
    const float* sinp = (const float*)d_in[3];
    const float* vs   = (const float*)d_in[4];
    float* out = (float*)d_out;

    cudaFuncSetAttribute(rnrope_mma_kernel,
                         cudaFuncAttributeMaxDynamicSharedMemorySize,
                         SMEM_FLOATS * (int)sizeof(float));
    build_q_kernel<<<1, 256>>>(vs);
    rnrope_mma_kernel<<<GRID, 128, SMEM_FLOATS * sizeof(float)>>>(q, k, cosp, sinp, out);
}